// round 13
// baseline (speedup 1.0000x reference)
#include <cuda_runtime.h>

#define NG      512
#define W_IMG   256
#define H_IMG   256
#define NEG_HALF_LOG2E (-0.7213475204444817f)   // -0.5 * log2(e)
#define LOG2EPS (-27.0f)                        // skip if max alpha < 2^-27

__device__ __forceinline__ float ex2_approx(float x) {
    float y; asm("ex2.approx.f32 %0, %1;" : "=f"(y) : "f"(x)); return y;
}
__device__ __forceinline__ float lg2_approx(float x) {
    float y; asm("lg2.approx.f32 %0, %1;" : "=f"(y) : "f"(x)); return y;
}
__device__ __forceinline__ float rcp_approx(float x) {
    float y; asm("rcp.approx.f32 %0, %1;" : "=f"(y) : "f"(x)); return y;
}

// One block per row, 256 threads = 4 groups × 64; each thread composites an
// ordered quarter of the survivors for 4 adjacent pixels (second-difference
// exponent). NEW: prep culls per (gaussian, x-half) with the clamped-vertex
// window test and builds TWO ordered compacted lists (px[0,128) / px[128,256)).
// A warp's lanes lie entirely in one half, so the mainloop iterates only its
// half's list — no per-iteration vote, no divergence. Partials combined
// exactly (compositing is an associative affine map).
__global__ __launch_bounds__(256) void Render_75617194213733_kernel(
    const float* __restrict__ means,    // [NG,2]
    const float* __restrict__ cov,      // [NG,2,2]
    const float* __restrict__ opac,     // [NG]
    const float* __restrict__ colors,   // [NG,3]
    float* __restrict__ out)            // [H,W,3]
{
    __shared__ float4 C[4 * NG];        // half0: [2j],[2j+1] at 0; half1 at 2*NG
                                        // [2j]=(mx,ka,kb*dy,kd*dy^2+lop), [2j+1]=(cr,cg,cb,2ka)
    __shared__ float4 Ppart[4][3 * 64]; // per-pixel partials, groups 1..3
    __shared__ int    sCnt0[16], sCnt1[16];
    __shared__ int    sBase0[16], sBase1[16];
    __shared__ int    sM0, sM1;

    const int tid  = threadIdx.x;
    const int lane = tid & 31;
    const int warp = tid >> 5;
    const float py = (float)blockIdx.x + 0.5f;

    // ── Fused prep + per-half x-window cull (2 gaussians/thread).
    float4 A[2], B[2];
    bool   kp0[2], kp1[2];
    unsigned b0[2], b1[2];
#pragma unroll
    for (int c = 0; c < 2; c++) {
        const int g = tid + 256 * c;
        float4 cv = ((const float4*)cov)[g];
        float2 mn = ((const float2*)means)[g];
        float  op = opac[g];
        float det = fmaf(cv.x, cv.w, -cv.y * cv.z);
        float s   = NEG_HALF_LOG2E * rcp_approx(det);
        float ka  = s * cv.w;                          // < 0
        float kb  = -s * (cv.y + cv.z);
        float kd  = s * cv.x;                          // < 0
        float lop = lg2_approx(op);
        float dy  = py - mn.y;
        float kbdy = kb * dy;
        float c1   = fmaf(kd * dy, dy, lop);           // kd*dy^2 + log2(op)
        // max of m(dx)=ka*dx^2+kbdy*dx+c1 over each half's x-window:
        // vertex dx* = -kbdy/(2ka) (ka<0 ⇒ max), clamped per window.
        float dxv = -kbdy * rcp_approx(ka + ka);
        float lo0 = 0.5f - mn.x,   hi0 = 127.5f - mn.x;
        float lo1 = 128.5f - mn.x, hi1 = 255.5f - mn.x;
        float d0 = fminf(fmaxf(dxv, lo0), hi0);
        float d1 = fminf(fmaxf(dxv, lo1), hi1);
        kp0[c] = fmaf(fmaf(ka, d0, kbdy), d0, c1) > LOG2EPS;
        kp1[c] = fmaf(fmaf(ka, d1, kbdy), d1, c1) > LOG2EPS;
        b0[c] = __ballot_sync(0xffffffffu, kp0[c]);
        b1[c] = __ballot_sync(0xffffffffu, kp1[c]);
        if (lane == 0) {
            sCnt0[c * 8 + warp] = __popc(b0[c]);
            sCnt1[c * 8 + warp] = __popc(b1[c]);
        }
        A[c] = make_float4(mn.x, ka, kbdy, c1);
        B[c] = make_float4(colors[3 * g + 0], colors[3 * g + 1],
                           colors[3 * g + 2], ka + ka);
    }
    __syncthreads();

    // ── Parallel shuffle scans: warp 0 -> half0 counts, warp 1 -> half1.
    if (warp < 2) {
        const int* cnt = warp ? sCnt1 : sCnt0;
        int* bas = warp ? sBase1 : sBase0;
        int c = (lane < 16) ? cnt[lane] : 0;
        int inc = c;
#pragma unroll
        for (int d = 1; d < 16; d <<= 1) {
            int n = __shfl_up_sync(0xffffffffu, inc, d);
            if (lane >= d) inc += n;
        }
        if (lane < 16) bas[lane] = inc - c;
        if (lane == 15) { if (warp) sM1 = inc; else sM0 = inc; }
    }
    __syncthreads();

#pragma unroll
    for (int c = 0; c < 2; c++) {
        const unsigned lm = (1u << lane) - 1u;
        if (kp0[c]) {
            int j = sBase0[c * 8 + warp] + __popc(b0[c] & lm);
            C[2 * j]     = A[c];
            C[2 * j + 1] = B[c];
        }
        if (kp1[c]) {
            int j = sBase1[c * 8 + warp] + __popc(b1[c] & lm);
            C[2 * NG + 2 * j]     = A[c];
            C[2 * NG + 2 * j + 1] = B[c];
        }
    }
    __syncthreads();

    // ── Mainloop: warp's lanes span one 128-px half; iterate that half's list.
    const int half  = warp & 1;                 // t<32 ⇔ warp even ⇔ px<128
    const int M     = half ? sM1 : sM0;
    const float4* __restrict__ Ch = C + half * (2 * NG);
    const int Mq    = (M + 3) >> 2;
    const int group = tid >> 6;
    const int t     = tid & 63;
    const int j0    = min(group * Mq, M);
    const int j1    = min(j0 + Mq, M);

    const float px = (float)(4 * t) + 0.5f;

    float T0 = 1.f, T1 = 1.f, T2 = 1.f, T3 = 1.f;
    float r0 = 0.f, g0 = 0.f, b0_ = 0.f;
    float r1 = 0.f, g1 = 0.f, b1_ = 0.f;
    float r2 = 0.f, g2 = 0.f, b2_ = 0.f;
    float r3 = 0.f, g3 = 0.f, b3_ = 0.f;

#pragma unroll 2
    for (int j = j0; j < j1; j++) {
        float4 pa = Ch[2 * j];          // mx, ka, kbdy, c1
        float4 pb = Ch[2 * j + 1];      // cr, cg, cb, 2ka
        float dx = px - pa.x;
        float t2 = fmaf(pa.y, dx, pa.z);          // ka*dx + kb*dy
        float m0 = fmaf(dx, t2, pa.w);            // exponent at px
        float s0 = t2 + fmaf(pa.y, dx, pa.y);     // first difference
        float m1 = m0 + s0;
        float s1 = s0 + pb.w;                     // second difference = 2ka
        float m2 = m1 + s1;
        float s2 = s1 + pb.w;
        float m3 = m2 + s2;

        float a0 = ex2_approx(m0);
        float a1 = ex2_approx(m1);
        float a2 = ex2_approx(m2);
        float a3 = ex2_approx(m3);

        float w0 = a0 * T0, w1 = a1 * T1, w2 = a2 * T2, w3 = a3 * T3;
        r0 = fmaf(w0, pb.x, r0); g0 = fmaf(w0, pb.y, g0); b0_ = fmaf(w0, pb.z, b0_);
        r1 = fmaf(w1, pb.x, r1); g1 = fmaf(w1, pb.y, g1); b1_ = fmaf(w1, pb.z, b1_);
        r2 = fmaf(w2, pb.x, r2); g2 = fmaf(w2, pb.y, g2); b2_ = fmaf(w2, pb.z, b2_);
        r3 = fmaf(w3, pb.x, r3); g3 = fmaf(w3, pb.y, g3); b3_ = fmaf(w3, pb.z, b3_);
        T0 *= 1.0000001f - a0;          // (1-a)+1e-7, off the critical chain
        T1 *= 1.0000001f - a1;
        T2 *= 1.0000001f - a2;
        T3 *= 1.0000001f - a3;
    }

    // ── Exact segment combine: C = C_a + T_a * C_b (fold groups 3→2→1→0).
    if (group != 0) {
        int pi = (group - 1) * 64 + t;
        Ppart[0][pi] = make_float4(r0, g0, b0_, T0);
        Ppart[1][pi] = make_float4(r1, g1, b1_, T1);
        Ppart[2][pi] = make_float4(r2, g2, b2_, T2);
        Ppart[3][pi] = make_float4(r3, g3, b3_, T3);
    }
    __syncthreads();
    if (group == 0) {
        float rl[4] = {r0, r1, r2, r3};
        float gl[4] = {g1, g1, g2, g3};   // placeholder fixed below
        gl[0] = g0;
        float bl[4] = {b0_, b1_, b2_, b3_};
        float Tl[4] = {T0, T1, T2, T3};
        float R[4], G[4], B[4];
#pragma unroll
        for (int p = 0; p < 4; p++) {
            float4 q1 = Ppart[p][t];
            float4 q2 = Ppart[p][64 + t];
            float4 q3 = Ppart[p][128 + t];
            float rr = fmaf(q2.w, q3.x, q2.x);
            float gg = fmaf(q2.w, q3.y, q2.y);
            float bb = fmaf(q2.w, q3.z, q2.z);
            rr = fmaf(q1.w, rr, q1.x);
            gg = fmaf(q1.w, gg, q1.y);
            bb = fmaf(q1.w, bb, q1.z);
            R[p] = fmaf(Tl[p], rr, rl[p]);
            G[p] = fmaf(Tl[p], gg, gl[p]);
            B[p] = fmaf(Tl[p], bb, bl[p]);
        }
        float4* o4 = (float4*)(out + (blockIdx.x * W_IMG + 4 * t) * 3);
        o4[0] = make_float4(R[0], G[0], B[0], R[1]);
        o4[1] = make_float4(G[1], B[1], R[2], G[2]);
        o4[2] = make_float4(B[2], R[3], G[3], B[3]);
    }
}

extern "C" void kernel_launch(void* const* d_in, const int* in_sizes, int n_in,
                              void* d_out, int out_size) {
    const float* means  = nullptr;
    const float* cov    = nullptr;
    const float* opac   = nullptr;
    const float* colors = nullptr;
    for (int i = 0; i < n_in; i++) {
        switch (in_sizes[i]) {
            case NG * 2: means  = (const float*)d_in[i]; break;
            case NG * 4: cov    = (const float*)d_in[i]; break;
            case NG:     opac   = (const float*)d_in[i]; break;
            case NG * 3: colors = (const float*)d_in[i]; break;
            default: break;
        }
    }
    Render_75617194213733_kernel<<<H_IMG, 256>>>(means, cov, opac, colors,
                                                 (float*)d_out);
}